// round 1
// baseline (speedup 1.0000x reference)
#include <cuda_runtime.h>
#include <math.h>

#define GFD   4096
#define DH    1024
#define BATCH 32
#define TK    196
#define BT    (BATCH * TK)   // 6272

// Output layout in d_out (float): c_img[32,1024] | coverage_new[32,196,1] | alpha[32,196,1]
#define OUT_C      0
#define OUT_COV    (BATCH * DH)                 // 32768
#define OUT_ALPHA  (BATCH * DH + BT)            // 39040

// ---------------- scratch (__device__ globals; no allocations allowed) ----------------
__device__ float g_W2[GFD * DH];       // Wg @ Gs            (16.8 MB)
__device__ float g_b2[DH];             // bg @ Gs + bgs
__device__ float g_gstar[BT * DH];     // gf @ W2 + b2       (25.7 MB)
__device__ float g_w[BT * DH];         // g_star @ Wgs       (25.7 MB)
__device__ float g_dec[BATCH * DH];    // s_t_hat @ Wdec + bdec
__device__ float g_scores[BT];
__device__ float g_alpha[BT];

// ---------------- 128x128x16 SGEMM, 8x8 micro-tile, fp32 ----------------
// C[M,N] = A[M,K] @ B[K,N] (+ bias[N]).  Requires M%128==0, N%128==0, K%16==0.
__global__ void __launch_bounds__(256) sgemm128(
    const float* __restrict__ A, const float* __restrict__ B,
    float* __restrict__ C, const float* __restrict__ bias,
    int M, int N, int K)
{
    __shared__ float As[16][128];   // transposed: As[k][m]
    __shared__ float Bs[16][128];   // Bs[k][n]

    const int bm  = blockIdx.y * 128;
    const int bn  = blockIdx.x * 128;
    const int tid = threadIdx.x;
    const int tx  = tid & 15;       // 0..15 -> n
    const int ty  = tid >> 4;       // 0..15 -> m

    // load mapping
    const int arow = tid >> 2;            // 0..63
    const int acol = (tid & 3) << 2;      // 0,4,8,12
    const int brow = tid >> 5;            // 0..7
    const int bcol = (tid & 31) << 2;     // 0..124

    const float* Aptr = A + (size_t)(bm + arow) * K + acol;
    const float* Bptr = B + (size_t)brow * N + bn + bcol;

    float acc[8][8];
#pragma unroll
    for (int i = 0; i < 8; i++)
#pragma unroll
        for (int j = 0; j < 8; j++) acc[i][j] = 0.f;

    for (int k0 = 0; k0 < K; k0 += 16) {
        float4 a0 = *(const float4*)(Aptr + k0);
        float4 a1 = *(const float4*)(Aptr + (size_t)64 * K + k0);
        float4 b0 = *(const float4*)(Bptr + (size_t)k0 * N);
        float4 b1 = *(const float4*)(Bptr + (size_t)(k0 + 8) * N);

        __syncthreads();
        As[acol + 0][arow] = a0.x;  As[acol + 1][arow] = a0.y;
        As[acol + 2][arow] = a0.z;  As[acol + 3][arow] = a0.w;
        As[acol + 0][arow + 64] = a1.x;  As[acol + 1][arow + 64] = a1.y;
        As[acol + 2][arow + 64] = a1.z;  As[acol + 3][arow + 64] = a1.w;
        *(float4*)&Bs[brow][bcol]     = b0;
        *(float4*)&Bs[brow + 8][bcol] = b1;
        __syncthreads();

#pragma unroll
        for (int kk = 0; kk < 16; kk++) {
            float ar[8], br[8];
            *(float4*)&ar[0] = *(const float4*)&As[kk][ty * 8];
            *(float4*)&ar[4] = *(const float4*)&As[kk][ty * 8 + 4];
            *(float4*)&br[0] = *(const float4*)&Bs[kk][tx * 8];
            *(float4*)&br[4] = *(const float4*)&Bs[kk][tx * 8 + 4];
#pragma unroll
            for (int i = 0; i < 8; i++)
#pragma unroll
                for (int j = 0; j < 8; j++)
                    acc[i][j] += ar[i] * br[j];
        }
    }

    float breg[8];
#pragma unroll
    for (int j = 0; j < 8; j++) breg[j] = bias ? bias[bn + tx * 8 + j] : 0.f;

#pragma unroll
    for (int i = 0; i < 8; i++) {
        const size_t row = (size_t)(bm + ty * 8 + i) * N + bn + tx * 8;
        float4 o0, o1;
        o0.x = acc[i][0] + breg[0];  o0.y = acc[i][1] + breg[1];
        o0.z = acc[i][2] + breg[2];  o0.w = acc[i][3] + breg[3];
        o1.x = acc[i][4] + breg[4];  o1.y = acc[i][5] + breg[5];
        o1.z = acc[i][6] + breg[6];  o1.w = acc[i][7] + breg[7];
        *(float4*)&C[row]     = o0;
        *(float4*)&C[row + 4] = o1;
    }
}

// ---------------- b2 = bg @ Gs + bgs ----------------
__global__ void __launch_bounds__(256) b2_kernel(
    const float* __restrict__ bg, const float* __restrict__ Gs,
    const float* __restrict__ bgs, float* __restrict__ b2)
{
    const int j = blockIdx.x * 256 + threadIdx.x;  // 0..DH-1
    float s = bgs[j];
#pragma unroll 8
    for (int i = 0; i < GFD; i++)
        s += bg[i] * Gs[(size_t)i * DH + j];
    b2[j] = s;
}

// ---------------- dec = s_t_hat @ Wdec + bdec ----------------
__global__ void __launch_bounds__(256) dec_kernel(
    const float* __restrict__ s_t_hat, const float* __restrict__ Wdec,
    const float* __restrict__ bdec, float* __restrict__ dec)
{
    const int idx = blockIdx.x * 256 + threadIdx.x;   // BATCH*DH
    const int b = idx >> 10;
    const int j = idx & (DH - 1);
    float s = bdec[j];
#pragma unroll 8
    for (int k = 0; k < DH; k++)
        s += s_t_hat[b * DH + k] * Wdec[(size_t)k * DH + j];
    dec[idx] = s;
}

// ---------------- scores[bt] = tanh(w + dec + cov) . v ----------------
__global__ void __launch_bounds__(256) scores_kernel(
    const float* __restrict__ w, const float* __restrict__ dec,
    const float* __restrict__ cov, const float* __restrict__ v,
    float* __restrict__ scores)
{
    const int bt = blockIdx.x;
    const int b  = bt / TK;
    const float c = cov[bt];
    float s = 0.f;
    for (int d = threadIdx.x; d < DH; d += 256)
        s += tanhf(w[(size_t)bt * DH + d] + dec[b * DH + d] + c) * v[d];

    __shared__ float red[8];
#pragma unroll
    for (int o = 16; o > 0; o >>= 1) s += __shfl_down_sync(0xffffffffu, s, o);
    if ((threadIdx.x & 31) == 0) red[threadIdx.x >> 5] = s;
    __syncthreads();
    if (threadIdx.x < 8) {
        s = red[threadIdx.x];
#pragma unroll
        for (int o = 4; o > 0; o >>= 1) s += __shfl_down_sync(0xffu, s, o);
        if (threadIdx.x == 0) scores[bt] = s;
    }
}

// ---------------- softmax over t (196 per batch); writes alpha + 2 outputs ----------------
__global__ void __launch_bounds__(256) softmax_kernel(
    const float* __restrict__ scores, const float* __restrict__ cov,
    float* __restrict__ alpha, float* __restrict__ out)
{
    const int b = blockIdx.x;
    const int t = threadIdx.x;
    __shared__ float red[8];
    __shared__ float smax, ssum;

    float sv = (t < TK) ? scores[b * TK + t] : -3.4e38f;

    float m = sv;
#pragma unroll
    for (int o = 16; o > 0; o >>= 1) m = fmaxf(m, __shfl_xor_sync(0xffffffffu, m, o));
    if ((t & 31) == 0) red[t >> 5] = m;
    __syncthreads();
    if (t < 8) {
        m = red[t];
#pragma unroll
        for (int o = 4; o > 0; o >>= 1) m = fmaxf(m, __shfl_xor_sync(0xffu, m, o));
        if (t == 0) smax = m;
    }
    __syncthreads();

    float e = (t < TK) ? expf(sv - smax) : 0.f;
    float su = e;
#pragma unroll
    for (int o = 16; o > 0; o >>= 1) su += __shfl_xor_sync(0xffffffffu, su, o);
    if ((t & 31) == 0) red[t >> 5] = su;
    __syncthreads();
    if (t < 8) {
        su = red[t];
#pragma unroll
        for (int o = 4; o > 0; o >>= 1) su += __shfl_xor_sync(0xffu, su, o);
        if (t == 0) ssum = su;
    }
    __syncthreads();

    if (t < TK) {
        const float a = e / ssum;
        alpha[b * TK + t] = a;
        out[OUT_ALPHA + b * TK + t] = a;
        out[OUT_COV   + b * TK + t] = cov[b * TK + t] + a;
    }
}

// ---------------- c_img[b,d] = sum_t alpha[b,t] * g_star[b,t,d] ----------------
__global__ void __launch_bounds__(256) cimg_kernel(
    const float* __restrict__ gstar, const float* __restrict__ alpha,
    float* __restrict__ out)
{
    const int b = blockIdx.y;
    const int d = blockIdx.x * 256 + threadIdx.x;
    __shared__ float sal[TK];
    if (threadIdx.x < TK) sal[threadIdx.x] = alpha[b * TK + threadIdx.x];
    __syncthreads();
    float s = 0.f;
#pragma unroll 4
    for (int t = 0; t < TK; t++)
        s += sal[t] * gstar[((size_t)(b * TK + t)) * DH + d];
    out[OUT_C + b * DH + d] = s;
}

// ---------------- launch ----------------
extern "C" void kernel_launch(void* const* d_in, const int* in_sizes, int n_in,
                              void* d_out, int out_size)
{
    const float* gf   = (const float*)d_in[0];   // [32,196,4096]
    const float* sth  = (const float*)d_in[1];   // [32,1024]
    const float* cov  = (const float*)d_in[2];   // [32,196,1]
    const float* Wg   = (const float*)d_in[3];   // [4096,4096]
    const float* bg   = (const float*)d_in[4];   // [4096]
    const float* Gs   = (const float*)d_in[5];   // [4096,1024]
    const float* bgs  = (const float*)d_in[6];   // [1024]
    const float* Wgs  = (const float*)d_in[7];   // [1024,1024]
    const float* Wdec = (const float*)d_in[8];   // [1024,1024]
    const float* bdec = (const float*)d_in[9];   // [1024]
    const float* v    = (const float*)d_in[10];  // [1024,1]
    float* out = (float*)d_out;

    float *W2p, *b2p, *gstarp, *wp, *decp, *scoresp, *alphap;
    cudaGetSymbolAddress((void**)&W2p,     g_W2);
    cudaGetSymbolAddress((void**)&b2p,     g_b2);
    cudaGetSymbolAddress((void**)&gstarp,  g_gstar);
    cudaGetSymbolAddress((void**)&wp,      g_w);
    cudaGetSymbolAddress((void**)&decp,    g_dec);
    cudaGetSymbolAddress((void**)&scoresp, g_scores);
    cudaGetSymbolAddress((void**)&alphap,  g_alpha);

    // b2 = bg @ Gs + bgs
    b2_kernel<<<DH / 256, 256>>>(bg, Gs, bgs, b2p);

    // W2 = Wg @ Gs                         [4096,1024]  (17.2 GMAC)
    {
        dim3 grid(DH / 128, GFD / 128);
        sgemm128<<<grid, 256>>>(Wg, Gs, W2p, nullptr, GFD, DH, GFD);
    }
    // g_star = gf @ W2 + b2                [6272,1024]  (26.3 GMAC)
    {
        dim3 grid(DH / 128, BT / 128);
        sgemm128<<<grid, 256>>>(gf, W2p, gstarp, b2p, BT, DH, GFD);
    }
    // w = g_star @ Wgs                     [6272,1024]  (6.6 GMAC)
    {
        dim3 grid(DH / 128, BT / 128);
        sgemm128<<<grid, 256>>>(gstarp, Wgs, wp, nullptr, BT, DH, DH);
    }

    // dec = s_t_hat @ Wdec + bdec
    dec_kernel<<<(BATCH * DH) / 256, 256>>>(sth, Wdec, bdec, decp);

    // scores = tanh(w + dec + cov) . v
    scores_kernel<<<BT, 256>>>(wp, decp, cov, v, scoresp);

    // softmax over regions; also writes coverage_new and alpha outputs
    softmax_kernel<<<BATCH, 256>>>(scoresp, cov, alphap, out);

    // c_img = sum_t alpha * g_star
    {
        dim3 grid(DH / 256, BATCH);
        cimg_kernel<<<grid, 256>>>(gstarp, alphap, out);
    }
}

// round 3
// speedup vs baseline: 2.5125x; 2.5125x over previous
#include <cuda_runtime.h>
#include <cuda_bf16.h>
#include <cstdint>
#include <math.h>

#define GFD   4096
#define DH    1024
#define BATCH 32
#define TK    196
#define BT    (BATCH * TK)   // 6272

// Output layout in d_out (float): c_img[32,1024] | coverage_new[32,196,1] | alpha[32,196,1]
#define OUT_C      0
#define OUT_COV    (BATCH * DH)
#define OUT_ALPHA  (BATCH * DH + BT)

// ============================ scratch (__device__ globals) ============================
__device__ __align__(1024) __nv_bfloat16 g_WgH[GFD * GFD];
__device__ __align__(1024) __nv_bfloat16 g_WgL[GFD * GFD];
__device__ __align__(1024) __nv_bfloat16 g_gfH[BT * GFD];
__device__ __align__(1024) __nv_bfloat16 g_gfL[BT * GFD];
__device__ __align__(1024) __nv_bfloat16 g_GsTH[DH * GFD];   // Gs^T  [DH, GFD]
__device__ __align__(1024) __nv_bfloat16 g_GsTL[DH * GFD];
__device__ __align__(1024) float         g_W2[GFD * DH];     // Wg@Gs [GFD, DH]
__device__ __align__(1024) __nv_bfloat16 g_W2TH[DH * GFD];   // W2^T  [DH, GFD]
__device__ __align__(1024) __nv_bfloat16 g_W2TL[DH * GFD];
__device__ __align__(1024) __nv_bfloat16 g_WgsTH[DH * DH];   // Wgs^T [DH, DH]
__device__ __align__(1024) __nv_bfloat16 g_WgsTL[DH * DH];
__device__ __align__(1024) float         g_gstar[BT * DH];
__device__ __align__(1024) __nv_bfloat16 g_gsH[BT * DH];
__device__ __align__(1024) __nv_bfloat16 g_gsL[BT * DH];
__device__ float g_b2[DH];
__device__ float g_dec[BATCH * DH];
__device__ float g_scores[BT];
__device__ float g_alpha[BT];

// ============================ helpers ============================
__device__ __forceinline__ uint32_t smem_u32(const void* p) {
    uint32_t a;
    asm("{ .reg .u64 t; cvta.to.shared.u64 t, %1; cvt.u32.u64 %0, t; }" : "=r"(a) : "l"(p));
    return a;
}
__device__ __forceinline__ void ldsm4(uint32_t* r, uint32_t addr) {
    asm volatile("ldmatrix.sync.aligned.m8n8.x4.shared.b16 {%0,%1,%2,%3}, [%4];"
                 : "=r"(r[0]), "=r"(r[1]), "=r"(r[2]), "=r"(r[3]) : "r"(addr));
}
__device__ __forceinline__ void mma16816(float* c, const uint32_t* a, const uint32_t* b) {
    asm volatile("mma.sync.aligned.m16n8k16.row.col.f32.bf16.bf16.f32 "
                 "{%0,%1,%2,%3}, {%4,%5,%6,%7}, {%8,%9}, {%0,%1,%2,%3};"
                 : "+f"(c[0]), "+f"(c[1]), "+f"(c[2]), "+f"(c[3])
                 : "r"(a[0]), "r"(a[1]), "r"(a[2]), "r"(a[3]), "r"(b[0]), "r"(b[1]));
}
__device__ __forceinline__ uint32_t swz(uint32_t off) {   // SW128: bits[6:4] ^= bits[9:7]
    return off ^ ((off >> 3) & 0x70);
}

// ============================ split-bf16 mma.sync GEMM ============================
// C[M,N] = Ah@Bh^T + Ah@Bl^T + Al@Bh^T, fp32 accum. A:[M,K] row-major, B:[N,K] row-major.
// CTA tile 128x128, K-tile 64, double-buffered cp.async. 8 warps, warp tile 64x32.
#define KTILE     64
#define TILE_B    16384                 // one 128x64 bf16 tile
#define STG_B     (4 * TILE_B)         // AH AL BH BL
#define SM_AH(s)  ((s) * STG_B)
#define SM_AL(s)  (SM_AH(s) + TILE_B)
#define SM_BH(s)  (SM_AH(s) + 2 * TILE_B)
#define SM_BL(s)  (SM_AH(s) + 3 * TILE_B)
#define GEMM_SMEM (2 * STG_B)          // 128 KB

__device__ __forceinline__ void issue_stage(
    uint32_t sb, int s, int kt,
    const __nv_bfloat16* __restrict__ Ah, const __nv_bfloat16* __restrict__ Al,
    const __nv_bfloat16* __restrict__ Bh, const __nv_bfloat16* __restrict__ Bl,
    int K, int bm, int bn, int tid)
{
    const int k0 = kt * KTILE;
#pragma unroll
    for (int i = 0; i < 4; i++) {
        int idx = tid + i * 256;
        int r = idx >> 3, c = idx & 7;
        uint32_t so = swz((uint32_t)(r * 128 + c * 16));
        size_t goA = (size_t)(bm + r) * K + k0 + c * 8;
        size_t goB = (size_t)(bn + r) * K + k0 + c * 8;
        asm volatile("cp.async.cg.shared.global [%0], [%1], 16;" :: "r"(sb + SM_AH(s) + so), "l"(Ah + goA) : "memory");
        asm volatile("cp.async.cg.shared.global [%0], [%1], 16;" :: "r"(sb + SM_AL(s) + so), "l"(Al + goA) : "memory");
        asm volatile("cp.async.cg.shared.global [%0], [%1], 16;" :: "r"(sb + SM_BH(s) + so), "l"(Bh + goB) : "memory");
        asm volatile("cp.async.cg.shared.global [%0], [%1], 16;" :: "r"(sb + SM_BL(s) + so), "l"(Bl + goB) : "memory");
    }
    asm volatile("cp.async.commit_group;" ::: "memory");
}

// mode 0: outF = D                                   (W2)
// mode 1: outF = D + bias; emit bf16 hi/lo           (g_star)
// mode 2: scores[m] += sum_n tanh(D + dec + cov)*v   (fused attention scores)
__global__ void __launch_bounds__(256, 1) gemm_mma(
    const __nv_bfloat16* __restrict__ Ah, const __nv_bfloat16* __restrict__ Al,
    const __nv_bfloat16* __restrict__ Bh, const __nv_bfloat16* __restrict__ Bl,
    int K, int KT, int mode,
    float* __restrict__ outF, const float* __restrict__ bias,
    __nv_bfloat16* __restrict__ outH, __nv_bfloat16* __restrict__ outL,
    const float* __restrict__ dec, const float* __restrict__ cov,
    const float* __restrict__ v, float* __restrict__ scores)
{
    extern __shared__ char smem[];
    const uint32_t sb  = smem_u32(smem);
    const int tid  = threadIdx.x;
    const int wid  = tid >> 5, lane = tid & 31;
    const int wm   = wid & 1,  wn   = wid >> 1;     // warp grid 2(m) x 4(n)
    const int bm   = blockIdx.y * 128, bn = blockIdx.x * 128;

    float acc[4][4][4];
#pragma unroll
    for (int a = 0; a < 4; a++)
#pragma unroll
        for (int b = 0; b < 4; b++)
#pragma unroll
            for (int c = 0; c < 4; c++) acc[a][b][c] = 0.f;

    // precomputed per-lane ldmatrix offsets (within-tile)
    const uint32_t a_row  = (uint32_t)(wm * 64 + (lane & 15));       // + mi*16
    const uint32_t a_kofs = (uint32_t)(((lane >> 4) & 1) * 16);      // + kk*32
    const uint32_t b_row  = (uint32_t)(wn * 32 + (lane & 7) + ((lane >> 4) & 1) * 8);  // + nq*16
    const uint32_t b_kofs = (uint32_t)(((lane >> 3) & 1) * 16);      // + kk*32

    issue_stage(sb, 0, 0, Ah, Al, Bh, Bl, K, bm, bn, tid);

    for (int kt = 0; kt < KT; kt++) {
        const int s = kt & 1;
        if (kt + 1 < KT) {
            issue_stage(sb, s ^ 1, kt + 1, Ah, Al, Bh, Bl, K, bm, bn, tid);
            asm volatile("cp.async.wait_group 1;" ::: "memory");
        } else {
            asm volatile("cp.async.wait_group 0;" ::: "memory");
        }
        __syncthreads();

        const uint32_t aH = sb + SM_AH(s), aL = sb + SM_AL(s);
        const uint32_t bH = sb + SM_BH(s), bL = sb + SM_BL(s);
#pragma unroll
        for (int kk = 0; kk < 4; kk++) {
            uint32_t fAh[4][4], fAl[4][4], fBh[2][4], fBl[2][4];
#pragma unroll
            for (int mi = 0; mi < 4; mi++) {
                uint32_t off = swz((a_row + mi * 16) * 128 + kk * 32 + a_kofs);
                ldsm4(fAh[mi], aH + off);
                ldsm4(fAl[mi], aL + off);
            }
#pragma unroll
            for (int nq = 0; nq < 2; nq++) {
                uint32_t off = swz((b_row + nq * 16) * 128 + kk * 32 + b_kofs);
                ldsm4(fBh[nq], bH + off);
                ldsm4(fBl[nq], bL + off);
            }
#pragma unroll
            for (int mi = 0; mi < 4; mi++)
#pragma unroll
                for (int nt = 0; nt < 4; nt++) {
                    const uint32_t* ph = &fBh[nt >> 1][(nt & 1) * 2];
                    const uint32_t* pl = &fBl[nt >> 1][(nt & 1) * 2];
                    mma16816(acc[mi][nt], fAh[mi], ph);
                    mma16816(acc[mi][nt], fAh[mi], pl);
                    mma16816(acc[mi][nt], fAl[mi], ph);
                }
        }
        __syncthreads();   // protect buffer s from next iteration's issue
    }

    // ---------------- epilogue (register accumulators) ----------------
    const int g = lane >> 2, tig = lane & 3;
#pragma unroll
    for (int mi = 0; mi < 4; mi++) {
#pragma unroll
        for (int h = 0; h < 2; h++) {
            const int m = bm + wm * 64 + mi * 16 + g + h * 8;
            float rsum = 0.f, cv = 0.f;
            int bofs = 0;
            if (mode == 2) { cv = cov[m]; bofs = (m / TK) * DH; }
#pragma unroll
            for (int nt = 0; nt < 4; nt++) {
#pragma unroll
                for (int e = 0; e < 2; e++) {
                    const int n = bn + wn * 32 + nt * 8 + 2 * tig + e;
                    float x = acc[mi][nt][h * 2 + e];
                    if (mode == 0) {
                        outF[(size_t)m * DH + n] = x;
                    } else if (mode == 1) {
                        x += bias[n];
                        outF[(size_t)m * DH + n] = x;
                        __nv_bfloat16 hh = __float2bfloat16(x);
                        outH[(size_t)m * DH + n] = hh;
                        outL[(size_t)m * DH + n] = __float2bfloat16(x - __bfloat162float(hh));
                    } else {
                        rsum += tanhf(x + dec[bofs + n] + cv) * v[n];
                    }
                }
            }
            if (mode == 2) {
                rsum += __shfl_xor_sync(0xffffffffu, rsum, 1);
                rsum += __shfl_xor_sync(0xffffffffu, rsum, 2);
                if (tig == 0) atomicAdd(&scores[m], rsum);
            }
        }
    }
}

// ============================ conversion kernels ============================
__global__ void __launch_bounds__(256) csplit(
    const float4* __restrict__ in, __nv_bfloat162* __restrict__ oh,
    __nv_bfloat162* __restrict__ ol, int n4)
{
    int i = blockIdx.x * 256 + threadIdx.x;
    if (i >= n4) return;
    float4 x = in[i];
    __nv_bfloat16 h0 = __float2bfloat16(x.x), h1 = __float2bfloat16(x.y);
    __nv_bfloat16 h2 = __float2bfloat16(x.z), h3 = __float2bfloat16(x.w);
    oh[2 * i]     = __halves2bfloat162(h0, h1);
    oh[2 * i + 1] = __halves2bfloat162(h2, h3);
    ol[2 * i]     = __halves2bfloat162(__float2bfloat16(x.x - __bfloat162float(h0)),
                                       __float2bfloat16(x.y - __bfloat162float(h1)));
    ol[2 * i + 1] = __halves2bfloat162(__float2bfloat16(x.z - __bfloat162float(h2)),
                                       __float2bfloat16(x.w - __bfloat162float(h3)));
}

// out[C,R] = split(in[R,C]^T)
__global__ void __launch_bounds__(256) tconv(
    const float* __restrict__ in, __nv_bfloat16* __restrict__ oh,
    __nv_bfloat16* __restrict__ ol, int R, int C)
{
    __shared__ float t[32][33];
    const int bx = blockIdx.x * 32, by = blockIdx.y * 32;
    const int x = threadIdx.x & 31, y = threadIdx.x >> 5;
#pragma unroll
    for (int i = 0; i < 32; i += 8)
        t[y + i][x] = in[(size_t)(by + y + i) * C + bx + x];
    __syncthreads();
#pragma unroll
    for (int i = 0; i < 32; i += 8) {
        float val = t[x][y + i];
        __nv_bfloat16 h = __float2bfloat16(val);
        size_t o = (size_t)(bx + y + i) * R + by + x;
        oh[o] = h;
        ol[o] = __float2bfloat16(val - __bfloat162float(h));
    }
}

// ============================ small kernels ============================
__global__ void __launch_bounds__(256) b2_kernel(
    const float* __restrict__ bg, const float* __restrict__ Gs,
    const float* __restrict__ bgs, float* __restrict__ b2)
{
    const int j = blockIdx.x * 256 + threadIdx.x;
    float s = bgs[j];
#pragma unroll 8
    for (int i = 0; i < GFD; i++) s += bg[i] * Gs[(size_t)i * DH + j];
    b2[j] = s;
}

__global__ void __launch_bounds__(256) dec_kernel(
    const float* __restrict__ s_t_hat, const float* __restrict__ Wdec,
    const float* __restrict__ bdec, float* __restrict__ dec)
{
    const int idx = blockIdx.x * 256 + threadIdx.x;
    const int b = idx >> 10, j = idx & (DH - 1);
    float s = bdec[j];
#pragma unroll 8
    for (int k = 0; k < DH; k++) s += s_t_hat[b * DH + k] * Wdec[(size_t)k * DH + j];
    dec[idx] = s;
}

__global__ void __launch_bounds__(256) softmax_kernel(
    const float* __restrict__ scores, const float* __restrict__ cov,
    float* __restrict__ alpha, float* __restrict__ out)
{
    const int b = blockIdx.x, t = threadIdx.x;
    __shared__ float red[8];
    __shared__ float smax, ssum;
    float sv = (t < TK) ? scores[b * TK + t] : -3.4e38f;

    float m = sv;
#pragma unroll
    for (int o = 16; o > 0; o >>= 1) m = fmaxf(m, __shfl_xor_sync(0xffffffffu, m, o));
    if ((t & 31) == 0) red[t >> 5] = m;
    __syncthreads();
    if (t < 8) {
        m = red[t];
#pragma unroll
        for (int o = 4; o > 0; o >>= 1) m = fmaxf(m, __shfl_xor_sync(0xffu, m, o));
        if (t == 0) smax = m;
    }
    __syncthreads();

    float e = (t < TK) ? expf(sv - smax) : 0.f;
    float su = e;
#pragma unroll
    for (int o = 16; o > 0; o >>= 1) su += __shfl_xor_sync(0xffffffffu, su, o);
    if ((t & 31) == 0) red[t >> 5] = su;
    __syncthreads();
    if (t < 8) {
        su = red[t];
#pragma unroll
        for (int o = 4; o > 0; o >>= 1) su += __shfl_xor_sync(0xffu, su, o);
        if (t == 0) ssum = su;
    }
    __syncthreads();

    if (t < TK) {
        const float a = e / ssum;
        alpha[b * TK + t] = a;
        out[OUT_ALPHA + b * TK + t] = a;
        out[OUT_COV + b * TK + t] = cov[b * TK + t] + a;
    }
}

__global__ void __launch_bounds__(256) cimg_kernel(
    const float* __restrict__ gstar, const float* __restrict__ alpha,
    float* __restrict__ out)
{
    const int b = blockIdx.y;
    const int d = blockIdx.x * 256 + threadIdx.x;
    __shared__ float sal[TK];
    if (threadIdx.x < TK) sal[threadIdx.x] = alpha[b * TK + threadIdx.x];
    __syncthreads();
    float s = 0.f;
#pragma unroll 4
    for (int t = 0; t < TK; t++)
        s += sal[t] * gstar[((size_t)(b * TK + t)) * DH + d];
    out[OUT_C + b * DH + d] = s;
}

// ============================ launch ============================
extern "C" void kernel_launch(void* const* d_in, const int* in_sizes, int n_in,
                              void* d_out, int out_size)
{
    const float* gf   = (const float*)d_in[0];
    const float* sth  = (const float*)d_in[1];
    const float* cov  = (const float*)d_in[2];
    const float* Wg   = (const float*)d_in[3];
    const float* bg   = (const float*)d_in[4];
    const float* Gs   = (const float*)d_in[5];
    const float* bgs  = (const float*)d_in[6];
    const float* Wgs  = (const float*)d_in[7];
    const float* Wdec = (const float*)d_in[8];
    const float* bdec = (const float*)d_in[9];
    const float* v    = (const float*)d_in[10];
    float* out = (float*)d_out;

    __nv_bfloat16 *WgH, *WgL, *gfH, *gfL, *GsTH, *GsTL, *W2TH, *W2TL, *WgsTH, *WgsTL, *gsH, *gsL;
    float *W2p, *gstarp, *b2p, *decp, *scoresp, *alphap;
    cudaGetSymbolAddress((void**)&WgH, g_WgH);     cudaGetSymbolAddress((void**)&WgL, g_WgL);
    cudaGetSymbolAddress((void**)&gfH, g_gfH);     cudaGetSymbolAddress((void**)&gfL, g_gfL);
    cudaGetSymbolAddress((void**)&GsTH, g_GsTH);   cudaGetSymbolAddress((void**)&GsTL, g_GsTL);
    cudaGetSymbolAddress((void**)&W2p, g_W2);
    cudaGetSymbolAddress((void**)&W2TH, g_W2TH);   cudaGetSymbolAddress((void**)&W2TL, g_W2TL);
    cudaGetSymbolAddress((void**)&WgsTH, g_WgsTH); cudaGetSymbolAddress((void**)&WgsTL, g_WgsTL);
    cudaGetSymbolAddress((void**)&gstarp, g_gstar);
    cudaGetSymbolAddress((void**)&gsH, g_gsH);     cudaGetSymbolAddress((void**)&gsL, g_gsL);
    cudaGetSymbolAddress((void**)&b2p, g_b2);      cudaGetSymbolAddress((void**)&decp, g_dec);
    cudaGetSymbolAddress((void**)&scoresp, g_scores);
    cudaGetSymbolAddress((void**)&alphap, g_alpha);

    cudaFuncSetAttribute(gemm_mma, cudaFuncAttributeMaxDynamicSharedMemorySize, GEMM_SMEM);

    // --- conversions ---
    csplit<<<(GFD * GFD / 4 + 255) / 256, 256>>>((const float4*)Wg,
        (__nv_bfloat162*)WgH, (__nv_bfloat162*)WgL, GFD * GFD / 4);
    csplit<<<(BT * GFD / 4 + 255) / 256, 256>>>((const float4*)gf,
        (__nv_bfloat162*)gfH, (__nv_bfloat162*)gfL, BT * GFD / 4);
    {   dim3 g(DH / 32, GFD / 32);  tconv<<<g, 256>>>(Gs, GsTH, GsTL, GFD, DH); }
    {   dim3 g(DH / 32, DH / 32);   tconv<<<g, 256>>>(Wgs, WgsTH, WgsTL, DH, DH); }

    // --- small precomputes ---
    b2_kernel<<<DH / 256, 256>>>(bg, Gs, bgs, b2p);
    dec_kernel<<<(BATCH * DH) / 256, 256>>>(sth, Wdec, bdec, decp);
    cudaMemsetAsync(scoresp, 0, BT * sizeof(float));

    // --- GEMM1: W2 = Wg @ Gs   [4096,1024], K=4096 ---
    {
        dim3 grid(DH / 128, GFD / 128);
        gemm_mma<<<grid, 256, GEMM_SMEM>>>(WgH, WgL, GsTH, GsTL, GFD, GFD / KTILE, 0,
            W2p, nullptr, nullptr, nullptr, nullptr, nullptr, nullptr, nullptr);
    }
    {   dim3 g(DH / 32, GFD / 32);  tconv<<<g, 256>>>(W2p, W2TH, W2TL, GFD, DH); }

    // --- GEMM2: g_star = gf @ W2 + b2   [6272,1024], K=4096 ---
    {
        dim3 grid(DH / 128, BT / 128);
        gemm_mma<<<grid, 256, GEMM_SMEM>>>(gfH, gfL, W2TH, W2TL, GFD, GFD / KTILE, 1,
            gstarp, b2p, gsH, gsL, nullptr, nullptr, nullptr, nullptr);
    }

    // --- GEMM3 (fused): scores = tanh(g_star@Wgs + dec + cov) . v   K=1024 ---
    {
        dim3 grid(DH / 128, BT / 128);
        gemm_mma<<<grid, 256, GEMM_SMEM>>>(gsH, gsL, WgsTH, WgsTL, DH, DH / KTILE, 2,
            nullptr, nullptr, nullptr, nullptr, decp, cov, v, scoresp);
    }

    // --- softmax + context ---
    softmax_kernel<<<BATCH, 256>>>(scoresp, cov, alphap, out);
    {   dim3 grid(DH / 256, BATCH);  cimg_kernel<<<grid, 256>>>(gstarp, alphap, out); }
}